// round 13
// baseline (speedup 1.0000x reference)
#include <cuda_runtime.h>
#include <cuda_fp16.h>
#include <math_constants.h>

#define NPTS 1024
#define DD   64
#define HA   256
#define TJ   256     // j-rows per tile (16 per warp x 16 warps)
#define NT   512
#define NW   16
#define NTILES (NPTS / TJ)

// ---------------- device scratch ----------------
__device__ float g_P [NPTS * DD];    // pos @ pW1
__device__ float g_A [NPTS * HA];    // (q + pb2) @ aW1 + ab1
__device__ float g_Bk[NPTS * HA];    // k @ aW1 (f32, packed to f16 below)
__device__ float g_V [NPTS * DD];    // v
__device__ float g_C [DD * HA];      // pW2 @ aW1
__device__ unsigned g_BkH[NPTS * HA / 2];  // Bk as f16x2 row-major
__device__ uint2 g_Cpk16 [4096];     // C packed as fp16 B-fragments
__device__ uint2 g_W2pk16[4096];     // aW2 packed fp16 B-fragments
__device__ uint2 g_Ppk16 [1024];     // pW2 packed fp16 B-fragments

// ---------------- helpers ----------------
__device__ __forceinline__ unsigned h2(float lo, float hi) {
    unsigned r;
    asm("cvt.rn.f16x2.f32 %0, %1, %2;" : "=r"(r) : "f"(hi), "f"(lo));  // first src -> upper half
    return r;
}
__device__ __forceinline__ void mma_f16(float* d, const unsigned* a,
                                        unsigned b0, unsigned b1) {
    asm volatile(
        "mma.sync.aligned.m16n8k16.row.col.f32.f16.f16.f32 "
        "{%0,%1,%2,%3}, {%4,%5,%6,%7}, {%8,%9}, {%0,%1,%2,%3};"
        : "+f"(d[0]), "+f"(d[1]), "+f"(d[2]), "+f"(d[3])
        : "r"(a[0]), "r"(a[1]), "r"(a[2]), "r"(a[3]), "r"(b0), "r"(b1));
}

// ---------------- kernel 1: per-point projections (4 pts/block) ----------------
__global__ void pt_proj_kernel(const float* __restrict__ x,
                               const float* __restrict__ pos,
                               const float* __restrict__ Wq,
                               const float* __restrict__ Wk,
                               const float* __restrict__ Wv,
                               const float* __restrict__ pW1,
                               const float* __restrict__ pb2,
                               const float* __restrict__ aW1,
                               const float* __restrict__ ab1)
{
    __shared__ float sx[4][DD], sq[4][DD], sk[4][DD];
    const int tid = threadIdx.x;
    const int pt  = tid >> 6;
    const int d   = tid & 63;
    const int i   = blockIdx.x * 4 + pt;

    sx[pt][d] = x[i * DD + d];
    __syncthreads();

    float q = 0.f, k = 0.f, v = 0.f;
#pragma unroll 8
    for (int c = 0; c < DD; ++c) {
        const float xc = sx[pt][c];
        q = fmaf(xc, Wq[c * DD + d], q);
        k = fmaf(xc, Wk[c * DD + d], k);
        v = fmaf(xc, Wv[c * DD + d], v);
    }
    g_P[i * DD + d] = pos[i * 2] * pW1[d] + pos[i * 2 + 1] * pW1[DD + d];
    g_V[i * DD + d] = v;
    sq[pt][d] = q + pb2[d];
    sk[pt][d] = k;
    __syncthreads();

    const int n = tid;
    float A0 = ab1[n], A1 = A0, A2 = A0, A3 = A0;
    float B0 = 0.f, B1 = 0.f, B2 = 0.f, B3 = 0.f;
#pragma unroll 8
    for (int c = 0; c < DD; ++c) {
        const float w = aW1[c * HA + n];
        A0 = fmaf(sq[0][c], w, A0); B0 = fmaf(sk[0][c], w, B0);
        A1 = fmaf(sq[1][c], w, A1); B1 = fmaf(sk[1][c], w, B1);
        A2 = fmaf(sq[2][c], w, A2); B2 = fmaf(sk[2][c], w, B2);
        A3 = fmaf(sq[3][c], w, A3); B3 = fmaf(sk[3][c], w, B3);
    }
    const int ib = blockIdx.x * 4;
    g_A [(ib + 0) * HA + n] = A0;  g_Bk[(ib + 0) * HA + n] = B0;
    g_A [(ib + 1) * HA + n] = A1;  g_Bk[(ib + 1) * HA + n] = B1;
    g_A [(ib + 2) * HA + n] = A2;  g_Bk[(ib + 2) * HA + n] = B2;
    g_A [(ib + 3) * HA + n] = A3;  g_Bk[(ib + 3) * HA + n] = B3;
}

// ---------------- kernel 2: C = pW2 @ aW1 ----------------
__global__ void pt_cmat_kernel(const float* __restrict__ pW2,
                               const float* __restrict__ aW1)
{
    const int c = blockIdx.x;
    const int n = threadIdx.x;
    float acc = 0.f;
#pragma unroll 8
    for (int d = 0; d < DD; ++d)
        acc = fmaf(pW2[c * DD + d], aW1[d * HA + n], acc);
    g_C[c * HA + n] = acc;
}

// ---------------- kernel 2b: pack Bk -> f16x2 row-major ----------------
__global__ void pt_packbk_kernel()
{
    const int gid = blockIdx.x * blockDim.x + threadIdx.x;  // 0..131071
    const int row = gid >> 7, c2 = gid & 127;
    g_BkH[gid] = h2(g_Bk[row * HA + 2 * c2], g_Bk[row * HA + 2 * c2 + 1]);
}

// ---------------- kernel 3: pack fp16 B-fragments ----------------
// m16n8k16 B layout: b0 = {B[k0+2t][n], B[k0+2t+1][n]}, b1 = {B[k0+2t+8][n], B[k0+2t+9][n]}
__global__ void pt_pack16_kernel(const float* __restrict__ aW2,
                                 const float* __restrict__ pW2)
{
    const int gid = blockIdx.x * blockDim.x + threadIdx.x;
    if (gid < 4096) {
        // Cpk16: B = C [64 c][256 n], index ((pass*8+na)*4+ka)*32+lane
        const int lane = gid & 31, ka = (gid >> 5) & 3, na = (gid >> 7) & 7, pass = gid >> 10;
        const int n  = 64 * pass + 8 * na + (lane >> 2);
        const int k0 = 16 * ka + 2 * (lane & 3);
        g_Cpk16[gid] = make_uint2(
            h2(g_C[(k0)     * HA + n], g_C[(k0 + 1) * HA + n]),
            h2(g_C[(k0 + 8) * HA + n], g_C[(k0 + 9) * HA + n]));
    } else if (gid < 8192) {
        // W2pk16: B = aW2 [256 k][64 d], index ((pass*8+na)*4+qa)*32+lane
        const int idx = gid - 4096;
        const int lane = idx & 31, qa = (idx >> 5) & 3, na = (idx >> 7) & 7, pass = idx >> 10;
        const int d  = 8 * na + (lane >> 2);
        const int k0 = 64 * pass + 16 * qa + 2 * (lane & 3);
        g_W2pk16[idx] = make_uint2(
            h2(aW2[(k0)     * DD + d], aW2[(k0 + 1) * DD + d]),
            h2(aW2[(k0 + 8) * DD + d], aW2[(k0 + 9) * DD + d]));
    } else if (gid < 9216) {
        // Ppk16: B = pW2 [64 c][64 d], index (na*4+ka)*32+lane
        const int idx = gid - 8192;
        const int lane = idx & 31, ka = (idx >> 5) & 3, na = idx >> 7;
        const int d  = 8 * na + (lane >> 2);
        const int k0 = 16 * ka + 2 * (lane & 3);
        g_Ppk16[idx] = make_uint2(
            h2(pW2[(k0)     * DD + d], pW2[(k0 + 1) * DD + d]),
            h2(pW2[(k0 + 8) * DD + d], pW2[(k0 + 9) * DD + d]));
    }
}

// ---------------- main fused kernel ----------------
// smem byte offsets
#define OFFB_CPK   0          // 32768  uint2 Cpk16
#define OFFB_W2PK  32768      // 32768  uint2 W2pk16
#define OFFB_PPK   65536      // 8192   uint2 Ppk16
#define OFFB_G     73728      // 36864  fp16 g tile [256 rows][72] (u32 stride 36)
#define OFFB_BASE  110592     // 1024   f32 Base[256]
#define OFFB_PBI   111616     // 256    f32 Pbi[64]
#define OFFB_MX    111872     // 256    f32 running max
#define OFFB_F     112128     // 256    f32 rescale factor
#define OFFB_R1    112384     // 4096   16 warps x 64 staging
#define OFFB_R2    116480     // 4096
#define SMEM_BYTES 120576

__global__ __launch_bounds__(NT, 1)
void pt_main_kernel(const float* __restrict__ pb1,
                    const float* __restrict__ pb2,
                    float* __restrict__ out)
{
    extern __shared__ __align__(16) unsigned char smx[];
    uint2*    sCpk  = (uint2*)(smx + OFFB_CPK);
    uint2*    sW2pk = (uint2*)(smx + OFFB_W2PK);
    uint2*    sPpk  = (uint2*)(smx + OFFB_PPK);
    unsigned* sG    = (unsigned*)(smx + OFFB_G);     // u32 view of f16x2, 36 u32/row
    float*    sBase = (float*)(smx + OFFB_BASE);
    float*    sPbi  = (float*)(smx + OFFB_PBI);
    float*    sMx   = (float*)(smx + OFFB_MX);
    float*    sF    = (float*)(smx + OFFB_F);
    float*    sR1   = (float*)(smx + OFFB_R1);
    float*    sR2   = (float*)(smx + OFFB_R2);

    const int tid  = threadIdx.x;
    const int i    = blockIdx.x;
    const int w    = tid >> 5;
    const int lane = tid & 31;
    const int lrow = lane >> 2;     // 0..7
    const int t4   = lane & 3;      // 0..3
    const int R0   = 16 * w;        // warp's j-row base within tile

    // ---- load persistent packed weights + per-i state ----
    {
        const uint4* c4 = (const uint4*)g_Cpk16;
        const uint4* w4 = (const uint4*)g_W2pk16;
        const uint4* p4 = (const uint4*)g_Ppk16;
        uint4* sc = (uint4*)sCpk;
        uint4* sw = (uint4*)sW2pk;
        uint4* sp = (uint4*)sPpk;
#pragma unroll
        for (int r = 0; r < 4; ++r) {
            sc[tid + r * NT] = c4[tid + r * NT];
            sw[tid + r * NT] = w4[tid + r * NT];
        }
        if (tid < 512) sp[tid] = p4[tid];
    }
    if (tid < HA) sBase[tid] = g_A[i * HA + tid];
    if (tid < DD) {
        sPbi[tid] = g_P[i * DD + tid] + pb1[tid];
        sMx[tid]  = -CUDART_INF_F;
    }
    __syncthreads();

    // per-thread channel-slot accumulators: slot (na,u) -> channel 8na+2t4+u
    float lacc[8][2], pacc[8][2];
#pragma unroll
    for (int na = 0; na < 8; ++na) {
        lacc[na][0] = lacc[na][1] = 0.f;
        pacc[na][0] = pacc[na][1] = 0.f;
    }

#pragma unroll 1
    for (int jt = 0; jt < NTILES; ++jt) {
        const int jb = jt * TJ;

        // ---- fill g tile fp16: g[j][c] = relu(Pbi[c] - P[jb+j][c]) ----
#pragma unroll 4
        for (int idx = tid; idx < TJ * 32; idx += NT) {
            const int row = idx >> 5, cp = idx & 31;
            const float2 pv = *(const float2*)&g_P[(jb + row) * DD + 2 * cp];
            const float2 pb = *(const float2*)&sPbi[2 * cp];
            sG[row * 36 + cp] = h2(fmaxf(pb.x - pv.x, 0.f), fmaxf(pb.y - pv.y, 0.f));
        }
        __syncthreads();

        // ---- A-fragments of g for this warp's 16 rows (k=64 -> 4 ka) ----
        unsigned ga[4][4];
#pragma unroll
        for (int ka = 0; ka < 4; ++ka) {
            const int rA = (R0 + lrow) * 36, rB = (R0 + lrow + 8) * 36;
            ga[ka][0] = sG[rA + 8 * ka + t4];
            ga[ka][1] = sG[rB + 8 * ka + t4];
            ga[ka][2] = sG[rA + 8 * ka + t4 + 4];
            ga[ka][3] = sG[rB + 8 * ka + t4 + 4];
        }

        float sim[8][4];
#pragma unroll
        for (int na = 0; na < 8; ++na)
#pragma unroll
            for (int u = 0; u < 4; ++u) sim[na][u] = 0.f;

#pragma unroll 1
        for (int pass = 0; pass < 4; ++pass) {
#pragma unroll
            for (int ka2 = 0; ka2 < 4; ++ka2) {
                // GEMM1 for na pair (2ka2, 2ka2+1)
                float hh[2][4];
#pragma unroll
                for (int p = 0; p < 2; ++p)
#pragma unroll
                    for (int u = 0; u < 4; ++u) hh[p][u] = 0.f;
#pragma unroll
                for (int ka = 0; ka < 4; ++ka) {
                    const uint2 b0 = sCpk[((pass * 8 + 2 * ka2)     * 4 + ka) * 32 + lane];
                    mma_f16(hh[0], ga[ka], b0.x, b0.y);
                    const uint2 b1 = sCpk[((pass * 8 + 2 * ka2 + 1) * 4 + ka) * 32 + lane];
                    mma_f16(hh[1], ga[ka], b1.x, b1.y);
                }

                // epilogue in registers: + Base - Bk(f16), relu, pack directly
                // into GEMM2 A-fragment (C-frag == A-frag layout identity)
                unsigned afr[4];
                const int rowA = jb + R0 + lrow;
#pragma unroll
                for (int p = 0; p < 2; ++p) {
                    const int na  = 2 * ka2 + p;
                    const int col = 64 * pass + 8 * na + 2 * t4;
                    const float2 bs = *(const float2*)&sBase[col];
                    const unsigned bkAu = g_BkH[rowA * (HA / 2) + (col >> 1)];
                    const unsigned bkBu = g_BkH[(rowA + 8) * (HA / 2) + (col >> 1)];
                    const float2 bkA = __half22float2(*(const __half2*)&bkAu);
                    const float2 bkB = __half22float2(*(const __half2*)&bkBu);
                    const float x0 = fmaxf(hh[p][0] + bs.x - bkA.x, 0.f);
                    const float x1 = fmaxf(hh[p][1] + bs.y - bkA.y, 0.f);
                    const float x2 = fmaxf(hh[p][2] + bs.x - bkB.x, 0.f);
                    const float x3 = fmaxf(hh[p][3] + bs.y - bkB.y, 0.f);
                    afr[2 * p]     = h2(x0, x1);
                    afr[2 * p + 1] = h2(x2, x3);
                }

                // GEMM2: sim += relu(h) @ aW2, k-group = (pass, ka2)
#pragma unroll
                for (int na2 = 0; na2 < 8; ++na2) {
                    const uint2 b = sW2pk[((pass * 8 + na2) * 4 + ka2) * 32 + lane];
                    mma_f16(sim[na2], afr, b.x, b.y);
                }
            }
        }

        // ---- softmax: per-slot max -> shfl over lrow -> cross-warp ----
        float mx[8][2];
#pragma unroll
        for (int na = 0; na < 8; ++na) {
            mx[na][0] = fmaxf(sim[na][0], sim[na][2]);
            mx[na][1] = fmaxf(sim[na][1], sim[na][3]);
        }
#pragma unroll
        for (int off = 4; off < 32; off <<= 1)
#pragma unroll
            for (int na = 0; na < 8; ++na) {
                mx[na][0] = fmaxf(mx[na][0], __shfl_xor_sync(0xffffffffu, mx[na][0], off));
                mx[na][1] = fmaxf(mx[na][1], __shfl_xor_sync(0xffffffffu, mx[na][1], off));
            }
        if (lane < 4) {
#pragma unroll
            for (int na = 0; na < 8; ++na) {
                sR1[w * 64 + 8 * na + 2 * lane]     = mx[na][0];
                sR1[w * 64 + 8 * na + 2 * lane + 1] = mx[na][1];
            }
        }
        __syncthreads();

        if (tid < DD) {
            float gm = sR1[tid];
#pragma unroll
            for (int ww = 1; ww < NW; ++ww) gm = fmaxf(gm, sR1[ww * 64 + tid]);
            const float nm = fmaxf(gm, sMx[tid]);
            sF[tid]  = __expf(sMx[tid] - nm);
            sMx[tid] = nm;
        }
        __syncthreads();

        // ---- fused rpe GEMM + e + accumulate (na pairs; rp transient) ----
        {
            const int rowA = jb + R0 + lrow;
#pragma unroll
            for (int na0 = 0; na0 < 8; na0 += 2) {
                float rpA[4] = {0.f, 0.f, 0.f, 0.f};
                float rpB[4] = {0.f, 0.f, 0.f, 0.f};
#pragma unroll
                for (int ka = 0; ka < 4; ++ka) {
                    const uint2 b0 = sPpk[((na0)     * 4 + ka) * 32 + lane];
                    mma_f16(rpA, ga[ka], b0.x, b0.y);
                    const uint2 b1 = sPpk[((na0 + 1) * 4 + ka) * 32 + lane];
                    mma_f16(rpB, ga[ka], b1.x, b1.y);
                }
#pragma unroll
                for (int p = 0; p < 2; ++p) {
                    const int na = na0 + p;
                    const float* rp = p ? rpB : rpA;
                    const int ch = 8 * na + 2 * t4;
                    const float2 nm2 = *(const float2*)&sMx[ch];
                    const float2 f2v = *(const float2*)&sF[ch];
                    const float2 vA = *(const float2*)&g_V[rowA * DD + ch];
                    const float2 vB = *(const float2*)&g_V[(rowA + 8) * DD + ch];
                    const float e00 = __expf(sim[na][0] - nm2.x);
                    const float e10 = __expf(sim[na][2] - nm2.x);
                    const float e01 = __expf(sim[na][1] - nm2.y);
                    const float e11 = __expf(sim[na][3] - nm2.y);
                    lacc[na][0] = lacc[na][0] * f2v.x + e00 + e10;
                    lacc[na][1] = lacc[na][1] * f2v.y + e01 + e11;
                    pacc[na][0] = pacc[na][0] * f2v.x
                                + e00 * (vA.x + rp[0]) + e10 * (vB.x + rp[2]);
                    pacc[na][1] = pacc[na][1] * f2v.y
                                + e01 * (vA.y + rp[1]) + e11 * (vB.y + rp[3]);
                }
            }
        }
        // next iteration's g-fill + its __syncthreads provide the hazard fence
    }

    // ---- final reduction: over lrow (shfl), then over warps (smem) ----
#pragma unroll
    for (int off = 4; off < 32; off <<= 1)
#pragma unroll
        for (int na = 0; na < 8; ++na) {
            lacc[na][0] += __shfl_xor_sync(0xffffffffu, lacc[na][0], off);
            lacc[na][1] += __shfl_xor_sync(0xffffffffu, lacc[na][1], off);
            pacc[na][0] += __shfl_xor_sync(0xffffffffu, pacc[na][0], off);
            pacc[na][1] += __shfl_xor_sync(0xffffffffu, pacc[na][1], off);
        }
    __syncthreads();
    if (lane < 4) {
#pragma unroll
        for (int na = 0; na < 8; ++na) {
            sR1[w * 64 + 8 * na + 2 * lane]     = lacc[na][0];
            sR1[w * 64 + 8 * na + 2 * lane + 1] = lacc[na][1];
            sR2[w * 64 + 8 * na + 2 * lane]     = pacc[na][0];
            sR2[w * 64 + 8 * na + 2 * lane + 1] = pacc[na][1];
        }
    }
    __syncthreads();
    if (tid < DD) {
        float L = 0.f, P = 0.f;
#pragma unroll
        for (int ww = 0; ww < NW; ++ww) {
            L += sR1[ww * 64 + tid];
            P += sR2[ww * 64 + tid];
        }
        out[i * DD + tid] = (P + L * pb2[tid]) / L;
    }
}

// ---------------- launch ----------------
extern "C" void kernel_launch(void* const* d_in, const int* in_sizes, int n_in,
                              void* d_out, int out_size)
{
    const float* x   = (const float*)d_in[0];
    const float* pos = (const float*)d_in[1];
    const float* Wq  = (const float*)d_in[2];
    const float* Wk  = (const float*)d_in[3];
    const float* Wv  = (const float*)d_in[4];
    const float* pW1 = (const float*)d_in[5];
    const float* pb1 = (const float*)d_in[6];
    const float* pW2 = (const float*)d_in[7];
    const float* pb2 = (const float*)d_in[8];
    const float* aW1 = (const float*)d_in[9];
    const float* ab1 = (const float*)d_in[10];
    const float* aW2 = (const float*)d_in[11];
    // ab2 constant over j -> cancels in per-channel softmax
    float* out = (float*)d_out;

    cudaFuncSetAttribute(pt_main_kernel,
                         cudaFuncAttributeMaxDynamicSharedMemorySize, SMEM_BYTES);

    pt_proj_kernel<<<NPTS / 4, 256>>>(x, pos, Wq, Wk, Wv, pW1, pb2, aW1, ab1);
    pt_cmat_kernel<<<DD, HA>>>(pW2, aW1);
    pt_packbk_kernel<<<NPTS * HA / 2 / 256, 256>>>();
    pt_pack16_kernel<<<36, 256>>>(aW2, pW2);
    pt_main_kernel<<<NPTS, NT, SMEM_BYTES>>>(pb1, pb2, out);
}

// round 14
// speedup vs baseline: 1.1623x; 1.1623x over previous
#include <cuda_runtime.h>
#include <cuda_fp16.h>
#include <math_constants.h>

#define NPTS 1024
#define DD   64
#define HA   256
#define TJ   256     // j-rows per tile (32 per warp x 8 warps)
#define NT   256
#define NW   8
#define NTILES (NPTS / TJ)

// ---------------- device scratch ----------------
__device__ float g_P [NPTS * DD];    // pos @ pW1
__device__ float g_A [NPTS * HA];    // (q + pb2) @ aW1 + ab1
__device__ float g_Bk[NPTS * HA];    // k @ aW1 (f32, packed to f16 below)
__device__ float g_V [NPTS * DD];    // v
__device__ float g_C [DD * HA];      // pW2 @ aW1
__device__ unsigned g_BkH[NPTS * HA / 2];  // Bk as f16x2 row-major
__device__ uint2 g_Cpk16 [4096];     // C packed as fp16 B-fragments
__device__ uint2 g_W2pk16[4096];     // aW2 packed fp16 B-fragments
__device__ uint2 g_Ppk16 [1024];     // pW2 packed fp16 B-fragments

// ---------------- helpers ----------------
__device__ __forceinline__ unsigned h2(float lo, float hi) {
    unsigned r;
    asm("cvt.rn.f16x2.f32 %0, %1, %2;" : "=r"(r) : "f"(hi), "f"(lo));  // first src -> upper half
    return r;
}
__device__ __forceinline__ void mma_f16(float* d, const unsigned* a,
                                        unsigned b0, unsigned b1) {
    asm volatile(
        "mma.sync.aligned.m16n8k16.row.col.f32.f16.f16.f32 "
        "{%0,%1,%2,%3}, {%4,%5,%6,%7}, {%8,%9}, {%0,%1,%2,%3};"
        : "+f"(d[0]), "+f"(d[1]), "+f"(d[2]), "+f"(d[3])
        : "r"(a[0]), "r"(a[1]), "r"(a[2]), "r"(a[3]), "r"(b0), "r"(b1));
}

// ---------------- kernel 1: per-point projections (4 pts/block) ----------------
__global__ void pt_proj_kernel(const float* __restrict__ x,
                               const float* __restrict__ pos,
                               const float* __restrict__ Wq,
                               const float* __restrict__ Wk,
                               const float* __restrict__ Wv,
                               const float* __restrict__ pW1,
                               const float* __restrict__ pb2,
                               const float* __restrict__ aW1,
                               const float* __restrict__ ab1)
{
    __shared__ float sx[4][DD], sq[4][DD], sk[4][DD];
    const int tid = threadIdx.x;
    const int pt  = tid >> 6;
    const int d   = tid & 63;
    const int i   = blockIdx.x * 4 + pt;

    sx[pt][d] = x[i * DD + d];
    __syncthreads();

    float q = 0.f, k = 0.f, v = 0.f;
#pragma unroll 8
    for (int c = 0; c < DD; ++c) {
        const float xc = sx[pt][c];
        q = fmaf(xc, Wq[c * DD + d], q);
        k = fmaf(xc, Wk[c * DD + d], k);
        v = fmaf(xc, Wv[c * DD + d], v);
    }
    g_P[i * DD + d] = pos[i * 2] * pW1[d] + pos[i * 2 + 1] * pW1[DD + d];
    g_V[i * DD + d] = v;
    sq[pt][d] = q + pb2[d];
    sk[pt][d] = k;
    __syncthreads();

    const int n = tid;
    float A0 = ab1[n], A1 = A0, A2 = A0, A3 = A0;
    float B0 = 0.f, B1 = 0.f, B2 = 0.f, B3 = 0.f;
#pragma unroll 8
    for (int c = 0; c < DD; ++c) {
        const float w = aW1[c * HA + n];
        A0 = fmaf(sq[0][c], w, A0); B0 = fmaf(sk[0][c], w, B0);
        A1 = fmaf(sq[1][c], w, A1); B1 = fmaf(sk[1][c], w, B1);
        A2 = fmaf(sq[2][c], w, A2); B2 = fmaf(sk[2][c], w, B2);
        A3 = fmaf(sq[3][c], w, A3); B3 = fmaf(sk[3][c], w, B3);
    }
    const int ib = blockIdx.x * 4;
    g_A [(ib + 0) * HA + n] = A0;  g_Bk[(ib + 0) * HA + n] = B0;
    g_A [(ib + 1) * HA + n] = A1;  g_Bk[(ib + 1) * HA + n] = B1;
    g_A [(ib + 2) * HA + n] = A2;  g_Bk[(ib + 2) * HA + n] = B2;
    g_A [(ib + 3) * HA + n] = A3;  g_Bk[(ib + 3) * HA + n] = B3;
}

// ---------------- kernel 2: C = pW2 @ aW1 ----------------
__global__ void pt_cmat_kernel(const float* __restrict__ pW2,
                               const float* __restrict__ aW1)
{
    const int c = blockIdx.x;
    const int n = threadIdx.x;
    float acc = 0.f;
#pragma unroll 8
    for (int d = 0; d < DD; ++d)
        acc = fmaf(pW2[c * DD + d], aW1[d * HA + n], acc);
    g_C[c * HA + n] = acc;
}

// ---------------- kernel 2b: pack Bk -> f16x2 row-major ----------------
__global__ void pt_packbk_kernel()
{
    const int gid = blockIdx.x * blockDim.x + threadIdx.x;  // 0..131071
    const int row = gid >> 7, c2 = gid & 127;
    g_BkH[gid] = h2(g_Bk[row * HA + 2 * c2], g_Bk[row * HA + 2 * c2 + 1]);
}

// ---------------- kernel 3: pack fp16 B-fragments ----------------
// m16n8k16 B layout: b0 = {B[k0+2t][n], B[k0+2t+1][n]}, b1 = {B[k0+2t+8][n], B[k0+2t+9][n]}
__global__ void pt_pack16_kernel(const float* __restrict__ aW2,
                                 const float* __restrict__ pW2)
{
    const int gid = blockIdx.x * blockDim.x + threadIdx.x;
    if (gid < 4096) {
        // Cpk16: B = C [64 c][256 n], index ((pass*8+na)*4+ka)*32+lane
        const int lane = gid & 31, ka = (gid >> 5) & 3, na = (gid >> 7) & 7, pass = gid >> 10;
        const int n  = 64 * pass + 8 * na + (lane >> 2);
        const int k0 = 16 * ka + 2 * (lane & 3);
        g_Cpk16[gid] = make_uint2(
            h2(g_C[(k0)     * HA + n], g_C[(k0 + 1) * HA + n]),
            h2(g_C[(k0 + 8) * HA + n], g_C[(k0 + 9) * HA + n]));
    } else if (gid < 8192) {
        // W2pk16: B = aW2 [256 k][64 d], index ((pass*8+na)*4+qa)*32+lane
        const int idx = gid - 4096;
        const int lane = idx & 31, qa = (idx >> 5) & 3, na = (idx >> 7) & 7, pass = idx >> 10;
        const int d  = 8 * na + (lane >> 2);
        const int k0 = 64 * pass + 16 * qa + 2 * (lane & 3);
        g_W2pk16[idx] = make_uint2(
            h2(aW2[(k0)     * DD + d], aW2[(k0 + 1) * DD + d]),
            h2(aW2[(k0 + 8) * DD + d], aW2[(k0 + 9) * DD + d]));
    } else if (gid < 9216) {
        // Ppk16: B = pW2 [64 c][64 d], index (na*4+ka)*32+lane
        const int idx = gid - 8192;
        const int lane = idx & 31, ka = (idx >> 5) & 3, na = idx >> 7;
        const int d  = 8 * na + (lane >> 2);
        const int k0 = 16 * ka + 2 * (lane & 3);
        g_Ppk16[idx] = make_uint2(
            h2(pW2[(k0)     * DD + d], pW2[(k0 + 1) * DD + d]),
            h2(pW2[(k0 + 8) * DD + d], pW2[(k0 + 9) * DD + d]));
    }
}

// ---------------- main fused kernel ----------------
// smem byte offsets
#define OFFB_CPK   0          // 32768  uint2 Cpk16
#define OFFB_W2PK  32768      // 32768  uint2 W2pk16
#define OFFB_PPK   65536      // 8192   uint2 Ppk16
#define OFFB_G     73728      // 36864  fp16 g tile [256 rows][72] (u32 stride 36)
#define OFFB_BASE  110592     // 1024   f32 Base[256]
#define OFFB_PBI   111616     // 256    f32 Pbi[64]
#define OFFB_MX    111872     // 256    f32 running max
#define OFFB_F     112128     // 256    f32 rescale factor
#define OFFB_R1    112384     // 2048   8 warps x 64 staging
#define OFFB_R2    114432     // 2048
#define SMEM_BYTES 116480

__global__ __launch_bounds__(NT, 1)
void pt_main_kernel(const float* __restrict__ pb1,
                    const float* __restrict__ pb2,
                    float* __restrict__ out)
{
    extern __shared__ __align__(16) unsigned char smx[];
    uint2*    sCpk  = (uint2*)(smx + OFFB_CPK);
    uint2*    sW2pk = (uint2*)(smx + OFFB_W2PK);
    uint2*    sPpk  = (uint2*)(smx + OFFB_PPK);
    unsigned* sG    = (unsigned*)(smx + OFFB_G);     // u32 view of f16x2, 36 u32/row
    float*    sBase = (float*)(smx + OFFB_BASE);
    float*    sPbi  = (float*)(smx + OFFB_PBI);
    float*    sMx   = (float*)(smx + OFFB_MX);
    float*    sF    = (float*)(smx + OFFB_F);
    float*    sR1   = (float*)(smx + OFFB_R1);
    float*    sR2   = (float*)(smx + OFFB_R2);

    const int tid  = threadIdx.x;
    const int i    = blockIdx.x;
    const int w    = tid >> 5;
    const int lane = tid & 31;
    const int lrow = lane >> 2;     // 0..7
    const int t4   = lane & 3;      // 0..3
    const int R0   = 32 * w;        // warp's j-row base within tile (2 groups of 16)

    // ---- load persistent packed weights + per-i state ----
    {
        const uint4* c4 = (const uint4*)g_Cpk16;
        const uint4* w4 = (const uint4*)g_W2pk16;
        const uint4* p4 = (const uint4*)g_Ppk16;
        uint4* sc = (uint4*)sCpk;
        uint4* sw = (uint4*)sW2pk;
        uint4* sp = (uint4*)sPpk;
#pragma unroll
        for (int r = 0; r < 8; ++r) {
            sc[tid + r * NT] = c4[tid + r * NT];
            sw[tid + r * NT] = w4[tid + r * NT];
        }
#pragma unroll
        for (int r = 0; r < 2; ++r) sp[tid + r * NT] = p4[tid + r * NT];
    }
    sBase[tid] = g_A[i * HA + tid];
    if (tid < DD) {
        sPbi[tid] = g_P[i * DD + tid] + pb1[tid];
        sMx[tid]  = -CUDART_INF_F;
    }
    __syncthreads();

    // per-thread channel-slot accumulators: slot (na,u) -> channel 8na+2t4+u
    float lacc[8][2], pacc[8][2];
#pragma unroll
    for (int na = 0; na < 8; ++na) {
        lacc[na][0] = lacc[na][1] = 0.f;
        pacc[na][0] = pacc[na][1] = 0.f;
    }

#pragma unroll 1
    for (int jt = 0; jt < NTILES; ++jt) {
        const int jb = jt * TJ;

        // ---- fill g tile fp16: g[j][c] = relu(Pbi[c] - P[jb+j][c]) ----
#pragma unroll 4
        for (int idx = tid; idx < TJ * 32; idx += NT) {
            const int row = idx >> 5, cp = idx & 31;
            const float2 pv = *(const float2*)&g_P[(jb + row) * DD + 2 * cp];
            const float2 pb = *(const float2*)&sPbi[2 * cp];
            sG[row * 36 + cp] = h2(fmaxf(pb.x - pv.x, 0.f), fmaxf(pb.y - pv.y, 0.f));
        }
        __syncthreads();

        // ---- A-fragments of g for both 16-row groups (k=64 -> 4 ka) ----
        unsigned ga[2][4][4];
#pragma unroll
        for (int gI = 0; gI < 2; ++gI)
#pragma unroll
            for (int ka = 0; ka < 4; ++ka) {
                const int rA = (R0 + 16 * gI + lrow) * 36;
                const int rB = (R0 + 16 * gI + lrow + 8) * 36;
                ga[gI][ka][0] = sG[rA + 8 * ka + t4];
                ga[gI][ka][1] = sG[rB + 8 * ka + t4];
                ga[gI][ka][2] = sG[rA + 8 * ka + t4 + 4];
                ga[gI][ka][3] = sG[rB + 8 * ka + t4 + 4];
            }

        float sim[2][8][4];
#pragma unroll
        for (int gI = 0; gI < 2; ++gI)
#pragma unroll
            for (int na = 0; na < 8; ++na)
#pragma unroll
                for (int u = 0; u < 4; ++u) sim[gI][na][u] = 0.f;

#pragma unroll 1
        for (int pass = 0; pass < 4; ++pass) {
            // GEMM1: h[32x64] = g @ C[:, pass*64 : +64]
            // 16 independent accumulation chains (2 gI x 8 na) for ILP
            float h[2][8][4];
#pragma unroll
            for (int gI = 0; gI < 2; ++gI)
#pragma unroll
                for (int na = 0; na < 8; ++na)
#pragma unroll
                    for (int u = 0; u < 4; ++u) h[gI][na][u] = 0.f;
#pragma unroll
            for (int ka = 0; ka < 4; ++ka)
#pragma unroll
                for (int na = 0; na < 8; ++na) {
                    const uint2 b = sCpk[((pass * 8 + na) * 4 + ka) * 32 + lane];
                    mma_f16(h[0][na], ga[0][ka], b.x, b.y);
                    mma_f16(h[1][na], ga[1][ka], b.x, b.y);
                }

            // epilogue in registers: + Base - Bk(f16), relu, pack directly
            // into GEMM2 A-fragments (C-frag == A-frag layout identity):
            // afr[gI][ka2] <- h[gI][2ka2] (slots 0,1) and h[gI][2ka2+1] (slots 2,3)
            unsigned afr[2][4][4];
#pragma unroll
            for (int gI = 0; gI < 2; ++gI) {
                const int rowA = jb + R0 + 16 * gI + lrow;
#pragma unroll
                for (int na = 0; na < 8; ++na) {
                    const int col = 64 * pass + 8 * na + 2 * t4;
                    const float2 bs = *(const float2*)&sBase[col];
                    const unsigned bkAu = g_BkH[rowA * (HA / 2) + (col >> 1)];
                    const unsigned bkBu = g_BkH[(rowA + 8) * (HA / 2) + (col >> 1)];
                    const float2 bkA = __half22float2(*(const __half2*)&bkAu);
                    const float2 bkB = __half22float2(*(const __half2*)&bkBu);
                    const float x0 = fmaxf(h[gI][na][0] + bs.x - bkA.x, 0.f);
                    const float x1 = fmaxf(h[gI][na][1] + bs.y - bkA.y, 0.f);
                    const float x2 = fmaxf(h[gI][na][2] + bs.x - bkB.x, 0.f);
                    const float x3 = fmaxf(h[gI][na][3] + bs.y - bkB.y, 0.f);
                    afr[gI][na >> 1][2 * (na & 1)]     = h2(x0, x1);
                    afr[gI][na >> 1][2 * (na & 1) + 1] = h2(x2, x3);
                }
            }

            // GEMM2: sim += relu(h) @ aW2[pass*64 : +64, :]
            // 16 independent sim chains (2 gI x 8 na2)
#pragma unroll
            for (int ka2 = 0; ka2 < 4; ++ka2)
#pragma unroll
                for (int na2 = 0; na2 < 8; ++na2) {
                    const uint2 b = sW2pk[((pass * 8 + na2) * 4 + ka2) * 32 + lane];
                    mma_f16(sim[0][na2], afr[0][ka2], b.x, b.y);
                    mma_f16(sim[1][na2], afr[1][ka2], b.x, b.y);
                }
        }

        // ---- softmax: per-slot max over both groups -> shfl -> cross-warp ----
        float mx[8][2];
#pragma unroll
        for (int na = 0; na < 8; ++na) {
            mx[na][0] = fmaxf(fmaxf(sim[0][na][0], sim[0][na][2]),
                              fmaxf(sim[1][na][0], sim[1][na][2]));
            mx[na][1] = fmaxf(fmaxf(sim[0][na][1], sim[0][na][3]),
                              fmaxf(sim[1][na][1], sim[1][na][3]));
        }
#pragma unroll
        for (int off = 4; off < 32; off <<= 1)
#pragma unroll
            for (int na = 0; na < 8; ++na) {
                mx[na][0] = fmaxf(mx[na][0], __shfl_xor_sync(0xffffffffu, mx[na][0], off));
                mx[na][1] = fmaxf(mx[na][1], __shfl_xor_sync(0xffffffffu, mx[na][1], off));
            }
        if (lane < 4) {
#pragma unroll
            for (int na = 0; na < 8; ++na) {
                sR1[w * 64 + 8 * na + 2 * lane]     = mx[na][0];
                sR1[w * 64 + 8 * na + 2 * lane + 1] = mx[na][1];
            }
        }
        __syncthreads();

        if (tid < DD) {
            float gm = sR1[tid];
#pragma unroll
            for (int ww = 1; ww < NW; ++ww) gm = fmaxf(gm, sR1[ww * 64 + tid]);
            const float nm = fmaxf(gm, sMx[tid]);
            sF[tid]  = __expf(sMx[tid] - nm);
            sMx[tid] = nm;
        }
        __syncthreads();

        // ---- fused rpe GEMM + e + accumulate (na pairs; rp transient) ----
#pragma unroll
        for (int na0 = 0; na0 < 8; na0 += 2) {
            float rp[2][2][4];
#pragma unroll
            for (int gI = 0; gI < 2; ++gI)
#pragma unroll
                for (int p = 0; p < 2; ++p)
#pragma unroll
                    for (int u = 0; u < 4; ++u) rp[gI][p][u] = 0.f;
#pragma unroll
            for (int ka = 0; ka < 4; ++ka) {
                const uint2 b0 = sPpk[((na0)     * 4 + ka) * 32 + lane];
                mma_f16(rp[0][0], ga[0][ka], b0.x, b0.y);
                mma_f16(rp[1][0], ga[1][ka], b0.x, b0.y);
                const uint2 b1 = sPpk[((na0 + 1) * 4 + ka) * 32 + lane];
                mma_f16(rp[0][1], ga[0][ka], b1.x, b1.y);
                mma_f16(rp[1][1], ga[1][ka], b1.x, b1.y);
            }
#pragma unroll
            for (int p = 0; p < 2; ++p) {
                const int na = na0 + p;
                const int ch = 8 * na + 2 * t4;
                const float2 nm2 = *(const float2*)&sMx[ch];
                const float2 f2v = *(const float2*)&sF[ch];
                float sl0 = 0.f, sl1 = 0.f, sp0 = 0.f, sp1 = 0.f;
#pragma unroll
                for (int gI = 0; gI < 2; ++gI) {
                    const int rowA = jb + R0 + 16 * gI + lrow;
                    const float2 vA = *(const float2*)&g_V[rowA * DD + ch];
                    const float2 vB = *(const float2*)&g_V[(rowA + 8) * DD + ch];
                    const float e00 = __expf(sim[gI][na][0] - nm2.x);
                    const float e10 = __expf(sim[gI][na][2] - nm2.x);
                    const float e01 = __expf(sim[gI][na][1] - nm2.y);
                    const float e11 = __expf(sim[gI][na][3] - nm2.y);
                    sl0 += e00 + e10;
                    sl1 += e01 + e11;
                    sp0 += e00 * (vA.x + rp[gI][p][0]) + e10 * (vB.x + rp[gI][p][2]);
                    sp1 += e01 * (vA.y + rp[gI][p][1]) + e11 * (vB.y + rp[gI][p][3]);
                }
                lacc[na][0] = lacc[na][0] * f2v.x + sl0;
                lacc[na][1] = lacc[na][1] * f2v.y + sl1;
                pacc[na][0] = pacc[na][0] * f2v.x + sp0;
                pacc[na][1] = pacc[na][1] * f2v.y + sp1;
            }
        }
        // next iteration's g-fill + its __syncthreads provide the hazard fence
    }

    // ---- final reduction: over lrow (shfl), then over warps (smem) ----
#pragma unroll
    for (int off = 4; off < 32; off <<= 1)
#pragma unroll
        for (int na = 0; na < 8; ++na) {
            lacc[na][0] += __shfl_xor_sync(0xffffffffu, lacc[na][0], off);
            lacc[na][1] += __shfl_xor_sync(0xffffffffu, lacc[na][1], off);
            pacc[na][0] += __shfl_xor_sync(0xffffffffu, pacc[na][0], off);
            pacc[na][1] += __shfl_xor_sync(0xffffffffu, pacc[na][1], off);
        }
    __syncthreads();
    if (lane < 4) {
#pragma unroll
        for (int na = 0; na < 8; ++na) {
            sR1[w * 64 + 8 * na + 2 * lane]     = lacc[na][0];
            sR1[w * 64 + 8 * na + 2 * lane + 1] = lacc[na][1];
            sR2[w * 64 + 8 * na + 2 * lane]     = pacc[na][0];
            sR2[w * 64 + 8 * na + 2 * lane + 1] = pacc[na][1];
        }
    }
    __syncthreads();
    if (tid < DD) {
        float L = 0.f, P = 0.f;
#pragma unroll
        for (int ww = 0; ww < NW; ++ww) {
            L += sR1[ww * 64 + tid];
            P += sR2[ww * 64 + tid];
        }
        out[i * DD + tid] = (P + L * pb2[tid]) / L;
    }
}

// ---------------- launch ----------------
extern "C" void kernel_launch(void* const* d_in, const int* in_sizes, int n_in,
                              void* d_out, int out_size)
{
    const float* x   = (const float*)d_in[0];
    const float* pos = (const float*)d_in[1];
    const float* Wq  = (const float*)d_in[2];
    const float* Wk  = (const float*)d_in[3];
    const float* Wv  = (const float*)d_in[4];
    const float* pW1 = (const float*)d_in[5];
    const float* pb1 = (const float*)d_in[6];
    const float* pW2 = (const float*)d_in[7];
    const float* pb2 = (const float*)d_in[8];
    const float* aW1 = (const float*)d_in[9];
    const float* ab1 = (const float*)d_in[10];
    const float* aW2 = (const float*)d_in[11];
    // ab2 constant over j -> cancels in per-channel softmax
    float* out = (float*)d_out;

    cudaFuncSetAttribute(pt_main_kernel,
                         cudaFuncAttributeMaxDynamicSharedMemorySize, SMEM_BYTES);

    pt_proj_kernel<<<NPTS / 4, 256>>>(x, pos, Wq, Wk, Wv, pW1, pb2, aW1, ab1);
    pt_cmat_kernel<<<DD, HA>>>(pW2, aW1);
    pt_packbk_kernel<<<NPTS * HA / 2 / 256, 256>>>();
    pt_pack16_kernel<<<36, 256>>>(aW2, pW2);
    pt_main_kernel<<<NPTS, NT, SMEM_BYTES>>>(pb1, pb2, out);
}